// round 3
// baseline (speedup 1.0000x reference)
#include <cuda_runtime.h>
#include <cuda_bf16.h>

// HashEmbedding: out[t, d] = sum_{h=0..3} weight_table[x[t,h] + 513*h] * emb_table[x[t,h]>>1][d]
// x is int32. Column-chunked smem-cached tables (4 chunks of 64 cols), 3 CTAs/SM.
// R3: software-pipeline the x-index load (prefetch next tile) so the per-iteration
// LDG->LDS->FMA->STG chain becomes LDS->FMA->STG with batched, latency-hidden loads.

#define NUM_HASHES 4
#define D 256
#define CH 64                  // columns per chunk
#define TPT (CH / 4)           // 16 threads per token (float4 each)
#define BLOCK_THREADS 512
#define TOK_PER_ITER (BLOCK_THREADS / TPT)   // 32 tokens per block-iteration
#define W_TABLE 2052           // 512*4 + 4
#define EMB_ROWS 256           // x in [0,512) -> idx = x>>1 in [0,256)
#define SMEM_FLOATS (EMB_ROWS * CH + W_TABLE)
#define SMEM_BYTES (SMEM_FLOATS * 4)

__global__ __launch_bounds__(BLOCK_THREADS, 3)
void hash_embedding_kernel(const int* __restrict__ x,
                           const float* __restrict__ weight_table,
                           const float* __restrict__ emb_table,
                           float* __restrict__ out,
                           int ntok)
{
    extern __shared__ float smem[];
    float* s_emb = smem;                      // [256][64]
    float* s_w   = smem + EMB_ROWS * CH;      // [2052]

    const int chunk = blockIdx.y;             // 0..3
    const int c0 = chunk * CH;

    // Stage embedding slice: 256 rows x 64 cols (float4) = 8 loads/thread.
    for (int i = threadIdx.x; i < EMB_ROWS * CH / 4; i += BLOCK_THREADS) {
        int r = i / (CH / 4);
        int c = (i % (CH / 4)) * 4;
        reinterpret_cast<float4*>(s_emb)[i] =
            *reinterpret_cast<const float4*>(emb_table + r * D + c0 + c);
    }
    // Stage weight table.
    for (int i = threadIdx.x; i < W_TABLE; i += BLOCK_THREADS) {
        s_w[i] = weight_table[i];
    }
    __syncthreads();

    const int grp  = threadIdx.x / TPT;       // token within iteration: 0..31
    const int lane = threadIdx.x % TPT;       // float4 slot within chunk: 0..15

    const int ntiles = ntok / TOK_PER_ITER;   // 2048 for 65536 tokens
    const int stride = gridDim.x;

    int tile = blockIdx.x;
    if (tile >= ntiles) return;

    // Prologue: load indices for the first tile.
    int t = tile * TOK_PER_ITER + grp;
    int4 xi = *reinterpret_cast<const int4*>(x + (long long)t * NUM_HASHES);

    #pragma unroll 1
    for (; tile < ntiles; tile += stride) {
        // Prefetch next tile's indices (clamped in-bounds; value unused on last iter).
        const int tile_next = (tile + stride < ntiles) ? (tile + stride) : tile;
        const int t_next = tile_next * TOK_PER_ITER + grp;
        const int4 xi_next =
            *reinterpret_cast<const int4*>(x + (long long)t_next * NUM_HASHES);

        const int i0 = xi.x, i1 = xi.y, i2 = xi.z, i3 = xi.w;

        // Per-sample weights (broadcast LDS within the 16-lane group).
        const float w0 = s_w[i0];
        const float w1 = s_w[i1 + 513];
        const float w2 = s_w[i2 + 1026];
        const float w3 = s_w[i3 + 1539];

        // Gather embedding slices (idx = x >> 1), conflict-free LDS.128.
        // Addresses are all ready at loop entry -> ptxas front-batches these.
        const float4 e0 = reinterpret_cast<const float4*>(s_emb + (i0 >> 1) * CH)[lane];
        const float4 e1 = reinterpret_cast<const float4*>(s_emb + (i1 >> 1) * CH)[lane];
        const float4 e2 = reinterpret_cast<const float4*>(s_emb + (i2 >> 1) * CH)[lane];
        const float4 e3 = reinterpret_cast<const float4*>(s_emb + (i3 >> 1) * CH)[lane];

        float4 r;
        r.x = w0 * e0.x + w1 * e1.x + w2 * e2.x + w3 * e3.x;
        r.y = w0 * e0.y + w1 * e1.y + w2 * e2.y + w3 * e3.y;
        r.z = w0 * e0.z + w1 * e1.z + w2 * e2.z + w3 * e3.z;
        r.w = w0 * e0.w + w1 * e1.w + w2 * e2.w + w3 * e3.w;

        *reinterpret_cast<float4*>(out + (long long)(tile * TOK_PER_ITER + grp) * D
                                   + c0 + lane * 4) = r;

        xi = xi_next;
    }
}

extern "C" void kernel_launch(void* const* d_in, const int* in_sizes, int n_in,
                              void* d_out, int out_size)
{
    const int*   x            = (const int*)d_in[0];
    const float* weight_table = (const float*)d_in[1];
    const float* emb_table    = (const float*)d_in[2];
    float*       out          = (float*)d_out;

    const int ntok = in_sizes[0] / NUM_HASHES;   // 65536

    cudaFuncSetAttribute(hash_embedding_kernel,
                         cudaFuncAttributeMaxDynamicSharedMemorySize, SMEM_BYTES);

    dim3 grid(111, D / CH);   // 111 x 4 = 444 blocks = 3 CTAs x 148 SMs
    hash_embedding_kernel<<<grid, BLOCK_THREADS, SMEM_BYTES>>>(
        x, weight_table, emb_table, out, ntok);
}

// round 4
// speedup vs baseline: 1.0014x; 1.0014x over previous
#include <cuda_runtime.h>
#include <cuda_bf16.h>

// HashEmbedding: out[t, d] = sum_{h=0..3} weight_table[x[t,h] + 513*h] * emb_table[x[t,h]>>1][d]
// x is int32.
// R4: CH=32 (8 column chunks), 384-thread blocks, 5 CTAs/SM (40.2 KB smem each).
// Per-token wavefront counts unchanged vs R3; occupancy 48 -> 60 warps/SM and
// staging prologue halved per block.

#define NUM_HASHES 4
#define D 256
#define CH 32                  // columns per chunk
#define TPT (CH / 4)           // 8 threads per token (float4 each)
#define BLOCK_THREADS 384
#define TOK_PER_ITER (BLOCK_THREADS / TPT)   // 48 tokens per block-iteration
#define W_TABLE 2052           // 512*4 + 4
#define EMB_ROWS 256           // x in [0,512) -> idx = x>>1 in [0,256)
#define SMEM_FLOATS (EMB_ROWS * CH + W_TABLE)
#define SMEM_BYTES (SMEM_FLOATS * 4)

__global__ __launch_bounds__(BLOCK_THREADS, 5)
void hash_embedding_kernel(const int* __restrict__ x,
                           const float* __restrict__ weight_table,
                           const float* __restrict__ emb_table,
                           float* __restrict__ out,
                           int ntok)
{
    extern __shared__ float smem[];
    float* s_emb = smem;                      // [256][32]
    float* s_w   = smem + EMB_ROWS * CH;      // [2052]

    const int chunk = blockIdx.y;             // 0..7
    const int c0 = chunk * CH;

    // Stage embedding slice: 256 rows x 32 cols (float4) = 2048 float4.
    for (int i = threadIdx.x; i < EMB_ROWS * CH / 4; i += BLOCK_THREADS) {
        int r = i / (CH / 4);
        int c = (i % (CH / 4)) * 4;
        reinterpret_cast<float4*>(s_emb)[i] =
            *reinterpret_cast<const float4*>(emb_table + r * D + c0 + c);
    }
    // Stage weight table.
    for (int i = threadIdx.x; i < W_TABLE; i += BLOCK_THREADS) {
        s_w[i] = weight_table[i];
    }
    __syncthreads();

    const int grp  = threadIdx.x / TPT;       // token within iteration: 0..47
    const int lane = threadIdx.x % TPT;       // float4 slot within chunk: 0..7

    const int ntiles = (ntok + TOK_PER_ITER - 1) / TOK_PER_ITER;  // 1366
    const int stride = gridDim.x;

    int tile = blockIdx.x;
    if (tile >= ntiles) return;

    // Prologue: load indices for the first tile (clamped).
    int t = tile * TOK_PER_ITER + grp;
    int t_ld = (t < ntok) ? t : 0;
    int4 xi = *reinterpret_cast<const int4*>(x + (long long)t_ld * NUM_HASHES);

    #pragma unroll 1
    for (; tile < ntiles; tile += stride) {
        // Prefetch next tile's indices (clamped; unused value on final iter).
        const int tile_next = (tile + stride < ntiles) ? (tile + stride) : tile;
        int tn = tile_next * TOK_PER_ITER + grp;
        if (tn >= ntok) tn = 0;
        const int4 xi_next =
            *reinterpret_cast<const int4*>(x + (long long)tn * NUM_HASHES);

        const int tcur = tile * TOK_PER_ITER + grp;
        if (tcur < ntok) {
            const int i0 = xi.x, i1 = xi.y, i2 = xi.z, i3 = xi.w;

            // Per-sample weights.
            const float w0 = s_w[i0];
            const float w1 = s_w[i1 + 513];
            const float w2 = s_w[i2 + 1026];
            const float w3 = s_w[i3 + 1539];

            // Gather embedding slices (idx = x >> 1), conflict-free LDS.128.
            const float4 e0 = reinterpret_cast<const float4*>(s_emb + (i0 >> 1) * CH)[lane];
            const float4 e1 = reinterpret_cast<const float4*>(s_emb + (i1 >> 1) * CH)[lane];
            const float4 e2 = reinterpret_cast<const float4*>(s_emb + (i2 >> 1) * CH)[lane];
            const float4 e3 = reinterpret_cast<const float4*>(s_emb + (i3 >> 1) * CH)[lane];

            float4 r;
            r.x = w0 * e0.x + w1 * e1.x + w2 * e2.x + w3 * e3.x;
            r.y = w0 * e0.y + w1 * e1.y + w2 * e2.y + w3 * e3.y;
            r.z = w0 * e0.z + w1 * e1.z + w2 * e2.z + w3 * e3.z;
            r.w = w0 * e0.w + w1 * e1.w + w2 * e2.w + w3 * e3.w;

            *reinterpret_cast<float4*>(out + (long long)tcur * D + c0 + lane * 4) = r;
        }
        xi = xi_next;
    }
}

extern "C" void kernel_launch(void* const* d_in, const int* in_sizes, int n_in,
                              void* d_out, int out_size)
{
    const int*   x            = (const int*)d_in[0];
    const float* weight_table = (const float*)d_in[1];
    const float* emb_table    = (const float*)d_in[2];
    float*       out          = (float*)d_out;

    const int ntok = in_sizes[0] / NUM_HASHES;   // 65536

    cudaFuncSetAttribute(hash_embedding_kernel,
                         cudaFuncAttributeMaxDynamicSharedMemorySize, SMEM_BYTES);

    dim3 grid(92, D / CH);   // 92 x 8 = 736 blocks ~= 5 CTAs x 148 SMs
    hash_embedding_kernel<<<grid, BLOCK_THREADS, SMEM_BYTES>>>(
        x, weight_table, emb_table, out, ntok);
}

// round 5
// speedup vs baseline: 1.1014x; 1.0998x over previous
#include <cuda_runtime.h>
#include <cuda_bf16.h>

// HashEmbedding: out[t, d] = sum_{h=0..3} weight_table[x[t,h] + 513*h] * emb_table[x[t,h]>>1][d]
// x is int32.
// R5: CH=64 with 2 float4 per thread per token (halves processed sequentially to
// cap registers). 512-thread blocks, 3 CTAs/SM, 64 tokens per block-iteration ->
// 1024 tiles exactly (no guards). Per-token fixed overhead (x load, weights,
// loop bookkeeping) amortized over 2x output bytes.

#define NUM_HASHES 4
#define D 256
#define CH 64                  // columns per chunk (2 x float4 per thread)
#define TPT 8                  // threads per token
#define BLOCK_THREADS 512
#define TOK_PER_ITER (BLOCK_THREADS / TPT)   // 64 tokens per block-iteration
#define W_TABLE 2052           // 512*4 + 4
#define EMB_ROWS 256
#define SMEM_FLOATS (EMB_ROWS * CH + W_TABLE)
#define SMEM_BYTES (SMEM_FLOATS * 4)

__global__ __launch_bounds__(BLOCK_THREADS, 3)
void hash_embedding_kernel(const int* __restrict__ x,
                           const float* __restrict__ weight_table,
                           const float* __restrict__ emb_table,
                           float* __restrict__ out,
                           int ntok)
{
    extern __shared__ float smem[];
    float* s_emb = smem;                      // [256][64]
    float* s_w   = smem + EMB_ROWS * CH;      // [2052]

    const int chunk = blockIdx.y;             // 0..3
    const int c0 = chunk * CH;

    // Stage embedding slice: 256 rows x 64 cols (float4) = 4096 float4, 8/thread.
    for (int i = threadIdx.x; i < EMB_ROWS * CH / 4; i += BLOCK_THREADS) {
        int r = i / (CH / 4);
        int c = (i % (CH / 4)) * 4;
        reinterpret_cast<float4*>(s_emb)[i] =
            *reinterpret_cast<const float4*>(emb_table + r * D + c0 + c);
    }
    for (int i = threadIdx.x; i < W_TABLE; i += BLOCK_THREADS) {
        s_w[i] = weight_table[i];
    }
    __syncthreads();

    const int grp  = threadIdx.x / TPT;       // token within iteration: 0..63
    const int lane = threadIdx.x % TPT;       // float4 slot: 0..7

    const int ntiles = ntok / TOK_PER_ITER;   // 1024 exactly for 65536 tokens
    const int stride = gridDim.x;

    int tile = blockIdx.x;

    // Prologue: indices for the first tile.
    int4 xi = *reinterpret_cast<const int4*>(
        x + (long long)(tile * TOK_PER_ITER + grp) * NUM_HASHES);

    #pragma unroll 1
    for (; tile < ntiles; tile += stride) {
        // Prefetch next tile's indices (clamped; unused on final iteration).
        const int tile_next = (tile + stride < ntiles) ? (tile + stride) : tile;
        const int4 xi_next = *reinterpret_cast<const int4*>(
            x + (long long)(tile_next * TOK_PER_ITER + grp) * NUM_HASHES);

        const int i0 = xi.x, i1 = xi.y, i2 = xi.z, i3 = xi.w;

        // Per-sample weights.
        const float w0 = s_w[i0];
        const float w1 = s_w[i1 + 513];
        const float w2 = s_w[i2 + 1026];
        const float w3 = s_w[i3 + 1539];

        // Row bases in the smem slice (idx = x >> 1).
        const float* r0 = s_emb + (i0 >> 1) * CH;
        const float* r1 = s_emb + (i1 >> 1) * CH;
        const float* r2 = s_emb + (i2 >> 1) * CH;
        const float* r3 = s_emb + (i3 >> 1) * CH;

        float* op = out + (long long)(tile * TOK_PER_ITER + grp) * D + c0 + lane * 4;

        // ---- half A: cols [lane*4, lane*4+4) ----
        {
            const float4 e0 = reinterpret_cast<const float4*>(r0)[lane];
            const float4 e1 = reinterpret_cast<const float4*>(r1)[lane];
            const float4 e2 = reinterpret_cast<const float4*>(r2)[lane];
            const float4 e3 = reinterpret_cast<const float4*>(r3)[lane];
            float4 r;
            r.x = w0 * e0.x + w1 * e1.x + w2 * e2.x + w3 * e3.x;
            r.y = w0 * e0.y + w1 * e1.y + w2 * e2.y + w3 * e3.y;
            r.z = w0 * e0.z + w1 * e1.z + w2 * e2.z + w3 * e3.z;
            r.w = w0 * e0.w + w1 * e1.w + w2 * e2.w + w3 * e3.w;
            *reinterpret_cast<float4*>(op) = r;
        }
        // ---- half B: cols [32 + lane*4, 32 + lane*4+4) ----
        {
            const float4 e0 = reinterpret_cast<const float4*>(r0)[lane + 8];
            const float4 e1 = reinterpret_cast<const float4*>(r1)[lane + 8];
            const float4 e2 = reinterpret_cast<const float4*>(r2)[lane + 8];
            const float4 e3 = reinterpret_cast<const float4*>(r3)[lane + 8];
            float4 r;
            r.x = w0 * e0.x + w1 * e1.x + w2 * e2.x + w3 * e3.x;
            r.y = w0 * e0.y + w1 * e1.y + w2 * e2.y + w3 * e3.y;
            r.z = w0 * e0.z + w1 * e1.z + w2 * e2.z + w3 * e3.z;
            r.w = w0 * e0.w + w1 * e1.w + w2 * e2.w + w3 * e3.w;
            *reinterpret_cast<float4*>(op + 32) = r;
        }

        xi = xi_next;
    }
}

extern "C" void kernel_launch(void* const* d_in, const int* in_sizes, int n_in,
                              void* d_out, int out_size)
{
    const int*   x            = (const int*)d_in[0];
    const float* weight_table = (const float*)d_in[1];
    const float* emb_table    = (const float*)d_in[2];
    float*       out          = (float*)d_out;

    const int ntok = in_sizes[0] / NUM_HASHES;   // 65536

    cudaFuncSetAttribute(hash_embedding_kernel,
                         cudaFuncAttributeMaxDynamicSharedMemorySize, SMEM_BYTES);

    dim3 grid(111, D / CH);   // 111 x 4 = 444 blocks = 3 CTAs x 148 SMs
    hash_embedding_kernel<<<grid, BLOCK_THREADS, SMEM_BYTES>>>(
        x, weight_table, emb_table, out, ntok);
}